// round 3
// baseline (speedup 1.0000x reference)
#include <cuda_runtime.h>
#include <cuda_bf16.h>

// SpectralGatingNetwork: y = irfft2(rfft2(x, ortho) * wc, ortho)
// x: (B=64, C=768, H=64, W=64) fp32, wc: (H=64, WF=33, C=768, 2)
// Per (b,c) image: 2D FFT64x64, gate, inverse. All custom shared-memory FFTs.

#define HCONST 64
#define WCONST 64
#define WF 33
#define CCH 768
#define BB 64
#define NIMG (BB * CCH)
#define GATE_PITCH (WF * HCONST)   // 2112 float2 per channel, layout [c][w][k]

__device__ float2 d_gate[CCH * GATE_PITCH];  // 12.97 MB scratch (allowed: __device__ global)

// ---------------- complex helpers ----------------
__device__ __forceinline__ float2 cadd(float2 a, float2 b) { return make_float2(a.x + b.x, a.y + b.y); }
__device__ __forceinline__ float2 csub(float2 a, float2 b) { return make_float2(a.x - b.x, a.y - b.y); }
__device__ __forceinline__ float2 cmul(float2 a, float2 b) {
    return make_float2(fmaf(a.x, b.x, -a.y * b.y), fmaf(a.x, b.y, a.y * b.x));
}
// a * conj(b)
__device__ __forceinline__ float2 cmulc(float2 a, float2 b) {
    return make_float2(fmaf(a.x, b.x, a.y * b.y), fmaf(a.y, b.x, -a.x * b.y));
}

// In-place natural-order 8-point DFT (DIT). INV=false: e^{-}, INV=true: e^{+} (unnormalized).
template <bool INV>
__device__ __forceinline__ void fft8(float2 a[8]) {
    const float s = 0.70710678118654752440f;
    // FFT4 on evens
    float2 t0 = cadd(a[0], a[4]), t1 = csub(a[0], a[4]);
    float2 t2 = cadd(a[2], a[6]), t3 = csub(a[2], a[6]);
    float2 E0 = cadd(t0, t2), E2 = csub(t0, t2);
    float2 E1, E3;
    if (!INV) { E1 = make_float2(t1.x + t3.y, t1.y - t3.x); E3 = make_float2(t1.x - t3.y, t1.y + t3.x); }
    else      { E1 = make_float2(t1.x - t3.y, t1.y + t3.x); E3 = make_float2(t1.x + t3.y, t1.y - t3.x); }
    // FFT4 on odds
    float2 u0 = cadd(a[1], a[5]), u1 = csub(a[1], a[5]);
    float2 u2 = cadd(a[3], a[7]), u3 = csub(a[3], a[7]);
    float2 O0 = cadd(u0, u2), O2 = csub(u0, u2);
    float2 O1, O3;
    if (!INV) { O1 = make_float2(u1.x + u3.y, u1.y - u3.x); O3 = make_float2(u1.x - u3.y, u1.y + u3.x); }
    else      { O1 = make_float2(u1.x - u3.y, u1.y + u3.x); O3 = make_float2(u1.x + u3.y, u1.y - u3.x); }
    // twiddles on odd branch
    float2 W1, W3, T2;
    if (!INV) {
        W1 = make_float2(s * (O1.x + O1.y), s * (O1.y - O1.x));   // * (s,-s)
        T2 = make_float2(O2.y, -O2.x);                            // * -i
        W3 = make_float2(s * (O3.y - O3.x), -s * (O3.x + O3.y));  // * (-s,-s)
    } else {
        W1 = make_float2(s * (O1.x - O1.y), s * (O1.y + O1.x));   // * (s,s)
        T2 = make_float2(-O2.y, O2.x);                            // * +i
        W3 = make_float2(-s * (O3.x + O3.y), s * (O3.x - O3.y));  // * (-s,s)
    }
    a[0] = cadd(E0, O0); a[4] = csub(E0, O0);
    a[1] = cadd(E1, W1); a[5] = csub(E1, W1);
    a[2] = cadd(E2, T2); a[6] = csub(E2, T2);
    a[3] = cadd(E3, W3); a[7] = csub(E3, W3);
}

// ---------------- gate prep: (H, WF, C, 2) -> [c][w][h] float2, with 1/4096 folded ----------------
__global__ void prep_gate_kernel(const float* __restrict__ cw) {
    int i = blockIdx.x * blockDim.x + threadIdx.x;
    const int TOT = HCONST * WF * CCH;
    if (i >= TOT) return;
    float re = cw[2 * i];
    float im = cw[2 * i + 1];
    int c = i % CCH;
    int kw = i / CCH;        // k*WF + w
    int w = kw % WF;
    int k = kw / WF;
    const float sc = 1.0f / 4096.0f;
    d_gate[c * GATE_PITCH + w * HCONST + k] = make_float2(re * sc, im * sc);
}

// ---------------- main kernel: one 64x64 image per CTA ----------------
__global__ __launch_bounds__(256) void sgn_kernel(const float* __restrict__ x,
                                                  float* __restrict__ out) {
    __shared__ float2 freq[64 * 34];   // [h][w] w in 0..32, pitch 34
    __shared__ float  buf[4096];       // input/output staging; aliased as ws (float2[2048])
    __shared__ float2 tws[64];         // e^{-2pi i p/64}
    float2* ws = reinterpret_cast<float2*>(buf);

    const int tid  = threadIdx.x;
    const int pair = tid >> 3;    // 0..31 (8 threads per FFT line)
    const int t    = tid & 7;
    const int bx   = blockIdx.x;
    const int c    = bx >> 6;     // consecutive CTAs share channel -> gate L2 reuse
    const int b    = bx & 63;
    const long img = ((long)b * CCH + c) * 4096;

    if (tid < 64) {
        float sv, cv;
        sincosf(-6.283185307179586477f * (float)tid / 64.0f, &sv, &cv);
        tws[tid] = make_float2(cv, sv);
    }

    // ---- load input (coalesced) ----
    {
        const float4* in4 = reinterpret_cast<const float4*>(x + img);
        float4* b4 = reinterpret_cast<float4*>(buf);
#pragma unroll
        for (int i = 0; i < 4; i++) b4[tid + 256 * i] = in4[tid + 256 * i];
    }
    __syncthreads();

    const int r1 = pair * 2, r2 = pair * 2 + 1;

    // ---- Stage 1: row r2c FFTs (two-for-one), result -> freq[h][0..32] ----
    {
        float2 a[8];
#pragma unroll
        for (int j = 0; j < 8; j++)
            a[j] = make_float2(buf[r1 * 64 + t + 8 * j], buf[r2 * 64 + t + 8 * j]);
        __syncthreads();                       // all input reads done before ws writes
        fft8<false>(a);
#pragma unroll
        for (int k = 1; k < 8; k++) a[k] = cmul(a[k], tws[t * k]);
#pragma unroll
        for (int k = 0; k < 8; k++) ws[pair * 64 + t * 8 + k] = a[k];
        __syncthreads();
        float2 bb[8];
#pragma unroll
        for (int n = 0; n < 8; n++) bb[n] = ws[pair * 64 + n * 8 + t];
        __syncthreads();
        fft8<false>(bb);                       // bb[k1] = Z[t + 8*k1]
#pragma unroll
        for (int k1 = 0; k1 < 8; k1++) ws[pair * 64 + t + 8 * k1] = bb[k1];
        __syncthreads();
        // unpack two-for-one: A -> freq[r1], B -> freq[r2], w in 0..32
#pragma unroll
        for (int q = 0; q < 4; q++) {
            int w = t + 8 * q;
            float2 Zw = ws[pair * 64 + w];
            float2 Zm = ws[pair * 64 + ((64 - w) & 63)];
            freq[r1 * 34 + w] = make_float2(0.5f * (Zw.x + Zm.x), 0.5f * (Zw.y - Zm.y));
            freq[r2 * 34 + w] = make_float2(0.5f * (Zw.y + Zm.y), 0.5f * (Zm.x - Zw.x));
        }
        if (t == 0) {
            float2 Z32 = ws[pair * 64 + 32];
            freq[r1 * 34 + 32] = make_float2(Z32.x, 0.0f);
            freq[r2 * 34 + 32] = make_float2(Z32.y, 0.0f);
        }
    }
    __syncthreads();

    // ---- Stage 2: column FFT (h), gate, inverse column FFT. 33 columns in 2 passes ----
    {
        const float2* gc = d_gate + c * GATE_PITCH;
#pragma unroll 1
        for (int pass = 0; pass < 2; pass++) {
            const int w = (pass == 0) ? pair : 32;
            const bool act = (pass == 0) || (pair == 0);
            float2 v[8];
            if (act) {
#pragma unroll
                for (int n2 = 0; n2 < 8; n2++) v[n2] = freq[(t + 8 * n2) * 34 + w];
                fft8<false>(v);
#pragma unroll
                for (int k = 1; k < 8; k++) v[k] = cmul(v[k], tws[t * k]);
            }
            __syncthreads();
            if (act) {
#pragma unroll
                for (int k = 0; k < 8; k++) ws[pair * 64 + t * 8 + k] = v[k];
            }
            __syncthreads();
            if (act) {
#pragma unroll
                for (int n = 0; n < 8; n++) v[n] = ws[pair * 64 + n * 8 + t];
                fft8<false>(v);                 // v[k1] = X[k = t + 8*k1]
#pragma unroll
                for (int k1 = 0; k1 < 8; k1++)
                    v[k1] = cmul(v[k1], gc[w * 64 + t + 8 * k1]);   // gate (1/4096 folded)
                // inverse: v indexed by kappa2 already matches
                fft8<true>(v);                  // -> T[t, m2]
#pragma unroll
                for (int m = 1; m < 8; m++) v[m] = cmulc(v[m], tws[t * m]);
            }
            __syncthreads();
            if (act) {
#pragma unroll
                for (int m = 0; m < 8; m++) ws[pair * 64 + t * 8 + m] = v[m];
            }
            __syncthreads();
            if (act) {
#pragma unroll
                for (int n = 0; n < 8; n++) v[n] = ws[pair * 64 + n * 8 + t];
                fft8<true>(v);                  // v[m1] = s[t + 8*m1]
#pragma unroll
                for (int m1 = 0; m1 < 8; m1++) freq[(t + 8 * m1) * 34 + w] = v[m1];
            }
            __syncthreads();
        }
    }

    // ---- Stage 3: inverse row c2r (two-for-one), forcing Re at w=0,32 ----
    {
        float2 z[8];
#pragma unroll
        for (int j = 0; j < 8; j++) {
            int idx = t + 8 * j;
            float2 Ze;
            if (idx == 0) {
                Ze = make_float2(freq[r1 * 34 + 0].x, freq[r2 * 34 + 0].x);
            } else if (idx == 32) {
                Ze = make_float2(freq[r1 * 34 + 32].x, freq[r2 * 34 + 32].x);
            } else if (idx < 32) {
                float2 A = freq[r1 * 34 + idx], B = freq[r2 * 34 + idx];
                Ze = make_float2(A.x - B.y, A.y + B.x);           // A + i*B
            } else {
                int k = 64 - idx;
                float2 A = freq[r1 * 34 + k], B = freq[r2 * 34 + k];
                Ze = make_float2(A.x + B.y, B.x - A.y);           // conj(A) + i*conj(B)
            }
            z[j] = Ze;
        }
        fft8<true>(z);
#pragma unroll
        for (int m = 1; m < 8; m++) z[m] = cmulc(z[m], tws[t * m]);
        __syncthreads();
#pragma unroll
        for (int m = 0; m < 8; m++) ws[pair * 64 + t * 8 + m] = z[m];
        __syncthreads();
        float2 v[8];
#pragma unroll
        for (int n = 0; n < 8; n++) v[n] = ws[pair * 64 + n * 8 + t];
        fft8<true>(v);                           // v[m1] = y1 + i*y2 at col t+8*m1
        __syncthreads();                         // all ws reads done before buf overwrite
#pragma unroll
        for (int m1 = 0; m1 < 8; m1++) {
            buf[r1 * 64 + t + 8 * m1] = v[m1].x;
            buf[r2 * 64 + t + 8 * m1] = v[m1].y;
        }
    }
    __syncthreads();

    // ---- store output (coalesced) ----
    {
        float4* o4 = reinterpret_cast<float4*>(out + img);
        const float4* b4 = reinterpret_cast<const float4*>(buf);
#pragma unroll
        for (int i = 0; i < 4; i++) o4[tid + 256 * i] = b4[tid + 256 * i];
    }
}

extern "C" void kernel_launch(void* const* d_in, const int* in_sizes, int n_in,
                              void* d_out, int out_size) {
    // identify inputs by size (x is much larger than complex_weight)
    const float* x  = (const float*)d_in[0];
    const float* cw = (const float*)d_in[1];
    if (n_in >= 2 && in_sizes[0] < in_sizes[1]) {
        x  = (const float*)d_in[1];
        cw = (const float*)d_in[0];
    }
    float* out = (float*)d_out;

    const int tot = HCONST * WF * CCH;
    prep_gate_kernel<<<(tot + 255) / 256, 256>>>(cw);
    sgn_kernel<<<NIMG, 256>>>(x, out);
}

// round 5
// speedup vs baseline: 1.4348x; 1.4348x over previous
#include <cuda_runtime.h>
#include <cuda_bf16.h>

// SpectralGatingNetwork: y = irfft2(rfft2(x, ortho) * wc, ortho)
// x: (B=64, C=768, H=64, W=64) fp32, wc: (H=64, WF=33, C=768, 2)
// One 64x64 image per CTA; custom shared-memory radix-8x8 FFT64.

#define WF 33
#define CCH 768
#define NIMG (64 * 768)
#define GATE_PITCH (WF * 64)   // 2112 float2 per channel, layout [c][w][k]

__device__ float2 d_gate[CCH * GATE_PITCH];  // ~13 MB, L2-resident

// ---------------- complex helpers ----------------
__device__ __forceinline__ float2 cadd(float2 a, float2 b) { return make_float2(a.x + b.x, a.y + b.y); }
__device__ __forceinline__ float2 csub(float2 a, float2 b) { return make_float2(a.x - b.x, a.y - b.y); }
__device__ __forceinline__ float2 cmul(float2 a, float2 b) {
    return make_float2(fmaf(a.x, b.x, -a.y * b.y), fmaf(a.x, b.y, a.y * b.x));
}
// a * conj(b)
__device__ __forceinline__ float2 cmulc(float2 a, float2 b) {
    return make_float2(fmaf(a.x, b.x, a.y * b.y), fmaf(a.y, b.x, -a.x * b.y));
}

// In-place natural-order 8-point DFT. INV=false: e^{-}, INV=true: e^{+} (unnormalized).
template <bool INV>
__device__ __forceinline__ void fft8(float2 a[8]) {
    const float s = 0.70710678118654752440f;
    float2 t0 = cadd(a[0], a[4]), t1 = csub(a[0], a[4]);
    float2 t2 = cadd(a[2], a[6]), t3 = csub(a[2], a[6]);
    float2 E0 = cadd(t0, t2), E2 = csub(t0, t2);
    float2 E1, E3;
    if (!INV) { E1 = make_float2(t1.x + t3.y, t1.y - t3.x); E3 = make_float2(t1.x - t3.y, t1.y + t3.x); }
    else      { E1 = make_float2(t1.x - t3.y, t1.y + t3.x); E3 = make_float2(t1.x + t3.y, t1.y - t3.x); }
    float2 u0 = cadd(a[1], a[5]), u1 = csub(a[1], a[5]);
    float2 u2 = cadd(a[3], a[7]), u3 = csub(a[3], a[7]);
    float2 O0 = cadd(u0, u2), O2 = csub(u0, u2);
    float2 O1, O3;
    if (!INV) { O1 = make_float2(u1.x + u3.y, u1.y - u3.x); O3 = make_float2(u1.x - u3.y, u1.y + u3.x); }
    else      { O1 = make_float2(u1.x - u3.y, u1.y + u3.x); O3 = make_float2(u1.x + u3.y, u1.y - u3.x); }
    float2 W1, W3, T2;
    if (!INV) {
        W1 = make_float2(s * (O1.x + O1.y), s * (O1.y - O1.x));
        T2 = make_float2(O2.y, -O2.x);
        W3 = make_float2(s * (O3.y - O3.x), -s * (O3.x + O3.y));
    } else {
        W1 = make_float2(s * (O1.x - O1.y), s * (O1.y + O1.x));
        T2 = make_float2(-O2.y, O2.x);
        W3 = make_float2(-s * (O3.x + O3.y), s * (O3.x - O3.y));
    }
    a[0] = cadd(E0, O0); a[4] = csub(E0, O0);
    a[1] = cadd(E1, W1); a[5] = csub(E1, W1);
    a[2] = cadd(E2, T2); a[6] = csub(E2, T2);
    a[3] = cadd(E3, W3); a[7] = csub(E3, W3);
}

// Conflict-free swizzled index into per-pair 64-float2 transpose scratch.
// Write pattern (col const across lanes) and read pattern (row const) are both
// bank-conflict-free per 16-lane half-warp.
__device__ __forceinline__ int wsidx(int p, int row, int col) {
    return p * 64 + (((row & 6) | ((p ^ col) & 1)) << 3) + ((row ^ col) & 7);
}

// ---------------- gate prep ----------------
// d_gate[c][w][k]: for w=1..31 raw gate * 1/4096.
// Slot w=0 holds G1[k], slot w=32 holds G2[k] (combined symmetrized gates for
// the packed real columns 0 and 32):
//   ge0[k]  = (g0[k]  + conj(g0[-k]))/2,  ge32 likewise
//   G1 = (ge0+ge32)/2,  G2 = (ge0-ge32)/2
__global__ void prep_gate_kernel(const float* __restrict__ cw) {
    int i = blockIdx.x * blockDim.x + threadIdx.x;
    const int TOT = 64 * WF * CCH;
    if (i >= TOT) return;
    int c = i % CCH;
    int kw = i / CCH;
    int w = kw % WF;
    int k = kw / WF;
    const float sc = 1.0f / 4096.0f;
    float2 g;
    if (w != 0 && w != 32) {
        int src = (k * WF + w) * CCH + c;
        g = make_float2(cw[2 * src] * sc, cw[2 * src + 1] * sc);
    } else {
        int km = (64 - k) & 63;
        int s0   = (k * WF + 0) * CCH + c,  s0m  = (km * WF + 0) * CCH + c;
        int s32  = (k * WF + 32) * CCH + c, s32m = (km * WF + 32) * CCH + c;
        float g0x = cw[2 * s0], g0y = cw[2 * s0 + 1];
        float g0mx = cw[2 * s0m], g0my = cw[2 * s0m + 1];
        float g32x = cw[2 * s32], g32y = cw[2 * s32 + 1];
        float g32mx = cw[2 * s32m], g32my = cw[2 * s32m + 1];
        float ge0x = 0.5f * (g0x + g0mx),   ge0y = 0.5f * (g0y - g0my);
        float ge32x = 0.5f * (g32x + g32mx), ge32y = 0.5f * (g32y - g32my);
        float rx, ry;
        if (w == 0) { rx = 0.5f * (ge0x + ge32x); ry = 0.5f * (ge0y + ge32y); }
        else        { rx = 0.5f * (ge0x - ge32x); ry = 0.5f * (ge0y - ge32y); }
        g = make_float2(rx * sc, ry * sc);
    }
    d_gate[c * GATE_PITCH + w * 64 + k] = g;
}

// ---------------- main kernel ----------------
__global__ void __launch_bounds__(256, 6) sgn_kernel(const float* __restrict__ x,
                                                     float* __restrict__ out) {
    __shared__ float2 freq[64 * 34];   // [h][w], pitch 34 (reads CF per half-warp)
    __shared__ float2 ws[32 * 64];     // swizzled transpose scratch, per-pair private
    __shared__ float2 tws[64];         // e^{-2pi i p/64}

    const int tid  = threadIdx.x;
    const int pair = tid >> 3;    // 0..31, 8 threads per FFT line
    const int t    = tid & 7;
    const int bx   = blockIdx.x;
    const int c    = bx >> 6;     // consecutive CTAs share channel -> gate L2 reuse
    const int b    = bx & 63;
    const long img = ((long)b * CCH + c) * 4096;

    if (tid < 64) {
        float sv, cv;
        sincosf(-6.283185307179586477f * (float)tid / 64.0f, &sv, &cv);
        tws[tid] = make_float2(cv, sv);
    }

    const int r1 = pair * 2, r2 = r1 + 1;

    // ---- Stage 1: row r2c FFTs (two-for-one), direct global loads ----
    {
        float2 a[8];
        const float* xr1 = x + img + r1 * 64 + t;
        const float* xr2 = x + img + r2 * 64 + t;
#pragma unroll
        for (int j = 0; j < 8; j++)
            a[j] = make_float2(__ldg(xr1 + 8 * j), __ldg(xr2 + 8 * j));
        __syncthreads();                       // tws ready (overlaps LDG latency)
        fft8<false>(a);
#pragma unroll
        for (int k = 1; k < 8; k++) a[k] = cmul(a[k], tws[t * k]);
#pragma unroll
        for (int k = 0; k < 8; k++) ws[wsidx(pair, t, k)] = a[k];
        __syncwarp();
        float2 z[8];
#pragma unroll
        for (int n = 0; n < 8; n++) z[n] = ws[wsidx(pair, n, t)];
        __syncwarp();
        fft8<false>(z);                        // z[k1] = Z[t + 8*k1]
#pragma unroll
        for (int k1 = 0; k1 < 8; k1++) ws[wsidx(pair, k1, t)] = z[k1];  // linear idx t+8k1
        __syncwarp();
        // two-for-one unpack -> freq rows r1, r2, w = 0..32
#pragma unroll
        for (int q = 0; q < 4; q++) {
            int w = t + 8 * q;
            float2 Zw = ws[wsidx(pair, q, t)];
            int m = (64 - w) & 63;
            float2 Zm = ws[wsidx(pair, m >> 3, m & 7)];
            freq[r1 * 34 + w] = make_float2(0.5f * (Zw.x + Zm.x), 0.5f * (Zw.y - Zm.y));
            freq[r2 * 34 + w] = make_float2(0.5f * (Zw.y + Zm.y), 0.5f * (Zm.x - Zw.x));
        }
        if (t == 0) {
            float2 Z32 = ws[wsidx(pair, 4, 0)];   // linear 32
            freq[r1 * 34 + 32] = make_float2(Z32.x, 0.0f);
            freq[r2 * 34 + 32] = make_float2(Z32.y, 0.0f);
        }
    }
    __syncthreads();

    // ---- Stage 2: column FFT, gate, inverse column FFT — single pass.
    // Pairs 1..31 -> columns 1..31. Pair 0 -> packed column (col0 + i*col32),
    // both real after the row r2c; gated with combined G1/G2. ----
    {
        const float2* gc = d_gate + c * GATE_PITCH;
        float2 v[8];
        if (pair == 0) {
#pragma unroll
            for (int n = 0; n < 8; n++) {
                int row = (t + 8 * n) * 34;
                v[n] = make_float2(freq[row].x, freq[row + 32].x);
            }
        } else {
#pragma unroll
            for (int n = 0; n < 8; n++) v[n] = freq[(t + 8 * n) * 34 + pair];
        }
        fft8<false>(v);
#pragma unroll
        for (int k = 1; k < 8; k++) v[k] = cmul(v[k], tws[t * k]);
#pragma unroll
        for (int k = 0; k < 8; k++) ws[wsidx(pair, t, k)] = v[k];
        __syncwarp();
#pragma unroll
        for (int n = 0; n < 8; n++) v[n] = ws[wsidx(pair, n, t)];
        __syncwarp();
        fft8<false>(v);                        // v[k1] = C[t + 8*k1]

        if (pair == 0) {
            // M[k1] = conj(C[(64-k)&63]); mirror via intra-pair shfl (lanes 0-7)
            float2 M[8];
            int src = (8 - t) & 7;
#pragma unroll
            for (int k1 = 0; k1 < 8; k1++) {
                float sx = __shfl_sync(0xFFu, v[7 - k1].x, src);
                float sy = __shfl_sync(0xFFu, v[7 - k1].y, src);
                M[k1] = make_float2(sx, -sy);
            }
            if (t == 0) {
#pragma unroll
                for (int k1 = 0; k1 < 8; k1++) {
                    float2 cc = v[(8 - k1) & 7];
                    M[k1] = make_float2(cc.x, -cc.y);
                }
            }
#pragma unroll
            for (int k1 = 0; k1 < 8; k1++) {
                float2 G1v = gc[t + 8 * k1];            // slot w=0
                float2 G2v = gc[32 * 64 + t + 8 * k1];  // slot w=32
                v[k1] = cadd(cmul(v[k1], G1v), cmul(M[k1], G2v));
            }
        } else {
#pragma unroll
            for (int k1 = 0; k1 < 8; k1++)
                v[k1] = cmul(v[k1], gc[pair * 64 + t + 8 * k1]);
        }

        fft8<true>(v);
#pragma unroll
        for (int m = 1; m < 8; m++) v[m] = cmulc(v[m], tws[t * m]);
#pragma unroll
        for (int m = 0; m < 8; m++) ws[wsidx(pair, t, m)] = v[m];
        __syncwarp();
#pragma unroll
        for (int n = 0; n < 8; n++) v[n] = ws[wsidx(pair, n, t)];
        fft8<true>(v);                         // v[m1] = s[t + 8*m1]
        if (pair == 0) {
#pragma unroll
            for (int m1 = 0; m1 < 8; m1++) {
                int row = (t + 8 * m1) * 34;
                freq[row]      = make_float2(v[m1].x, 0.0f);   // real col 0
                freq[row + 32] = make_float2(v[m1].y, 0.0f);   // real col 32
            }
        } else {
#pragma unroll
            for (int m1 = 0; m1 < 8; m1++) freq[(t + 8 * m1) * 34 + pair] = v[m1];
        }
    }
    __syncthreads();

    // ---- Stage 3: inverse row c2r (two-for-one), direct global stores ----
    {
        float2 z[8];
#pragma unroll
        for (int j = 0; j < 8; j++) {
            int idx = t + 8 * j;
            float2 Ze;
            if (idx == 0) {
                Ze = make_float2(freq[r1 * 34].x, freq[r2 * 34].x);
            } else if (idx == 32) {
                Ze = make_float2(freq[r1 * 34 + 32].x, freq[r2 * 34 + 32].x);
            } else if (idx < 32) {
                float2 A = freq[r1 * 34 + idx], Bv = freq[r2 * 34 + idx];
                Ze = make_float2(A.x - Bv.y, A.y + Bv.x);          // A + i*B
            } else {
                int k2 = 64 - idx;
                float2 A = freq[r1 * 34 + k2], Bv = freq[r2 * 34 + k2];
                Ze = make_float2(A.x + Bv.y, Bv.x - A.y);          // conj(A) + i*conj(B)
            }
            z[j] = Ze;
        }
        fft8<true>(z);
#pragma unroll
        for (int m = 1; m < 8; m++) z[m] = cmulc(z[m], tws[t * m]);
#pragma unroll
        for (int m = 0; m < 8; m++) ws[wsidx(pair, t, m)] = z[m];
        __syncwarp();
#pragma unroll
        for (int n = 0; n < 8; n++) z[n] = ws[wsidx(pair, n, t)];
        fft8<true>(z);                          // z[m1] = y1 + i*y2 at col t+8*m1
        float* o1 = out + img + r1 * 64 + t;
        float* o2 = out + img + r2 * 64 + t;
#pragma unroll
        for (int m1 = 0; m1 < 8; m1++) {
            o1[8 * m1] = z[m1].x;
            o2[8 * m1] = z[m1].y;
        }
    }
}

extern "C" void kernel_launch(void* const* d_in, const int* in_sizes, int n_in,
                              void* d_out, int out_size) {
    const float* x  = (const float*)d_in[0];
    const float* cw = (const float*)d_in[1];
    if (n_in >= 2 && in_sizes[0] < in_sizes[1]) {
        x  = (const float*)d_in[1];
        cw = (const float*)d_in[0];
    }
    float* out = (float*)d_out;

    const int tot = 64 * WF * CCH;
    prep_gate_kernel<<<(tot + 255) / 256, 256>>>(cw);
    sgn_kernel<<<NIMG, 256>>>(x, out);
}